// round 2
// baseline (speedup 1.0000x reference)
#include <cuda_runtime.h>
#include <cstdint>

typedef unsigned long long u64;

#define TT 200
#define BB 64
#define DD 300
#define DP 304
#define HH 512
#define G4 2048
#define LL 7

// ---------------- scratch (static device allocations; no cudaMalloc) --------
__device__ float g_X[(size_t)TT * BB * DP];          // gathered embeddings, padded K
__device__ float g_Z[(size_t)TT * BB * G4];          // input-projection buffer (reused per layer)
__device__ float g_H[(size_t)(TT + 1) * BB * HH];    // hidden states, slot 0 = zeros
__device__ float g_C[BB * HH];                       // cell state (reused per layer)
__device__ float g_WhP[3][(size_t)G4 * HH];          // permuted recurrent weights [u*4+g][k]

// ---------------- helpers ---------------------------------------------------
__device__ __forceinline__ u64 ffma2(u64 a, u64 b, u64 c) {
    u64 d;
    asm("fma.rn.f32x2 %0, %1, %2, %3;" : "=l"(d) : "l"(a), "l"(b), "l"(c));
    return d;
}
__device__ __forceinline__ float lo32(u64 v) { return __uint_as_float((unsigned)v); }
__device__ __forceinline__ float hi32(u64 v) { return __uint_as_float((unsigned)(v >> 32)); }
__device__ __forceinline__ float sigmoidf_(float x) { return 1.f / (1.f + __expf(-x)); }

// ---------------- embedding gather (time-major, zero-padded K) --------------
__global__ void gather_kernel(const int* __restrict__ ids, const float* __restrict__ emb) {
    size_t idx = (size_t)blockIdx.x * 256 + threadIdx.x;
    if (idx >= (size_t)TT * BB * DP) return;
    int d = (int)(idx % DP);
    int tb = (int)(idx / DP);
    int t = tb / BB, b = tb % BB;
    float v = 0.f;
    if (d < DD) {
        int id = ids[b * TT + t];
        v = emb[(size_t)id * DD + d];
    }
    g_X[idx] = v;
}

// ---------------- permute Wh[k][g*512+u] -> WhP[u*4+g][k] -------------------
__global__ void prep_whp(const float* __restrict__ Wh, int layer) {
    int r = blockIdx.x;            // 0..2047
    int u = r >> 2, g = r & 3;
    int col = g * HH + u;
    for (int k = threadIdx.x; k < HH; k += 256)
        g_WhP[layer][(size_t)r * HH + k] = Wh[(size_t)k * G4 + col];
}

// ---------------- tiled fp32 GEMM with bias:  C[M,N] = A[M,K]@W[K,N] + b ----
// BM=BN=64, BK=16, 256 threads, 4x4 micro-tile, k-paired FFMA2 accumulators.
__global__ void __launch_bounds__(256) gemm_bias(
    const float* __restrict__ A, int lda,
    const float* __restrict__ W, const float* __restrict__ bias,
    float* __restrict__ C, int N, int Kpad, int Kreal)
{
    __shared__ u64 sA[8][64];   // [k2][m]   pairs over k
    __shared__ u64 sB[8][64];   // [k2][n]   pairs over k

    int tid = threadIdx.x;
    int n0 = blockIdx.x * 64, m0 = blockIdx.y * 64;
    int tx = tid & 15, ty = tid >> 4;

    u64 acc[4][4];
#pragma unroll
    for (int i = 0; i < 4; i++)
#pragma unroll
        for (int j = 0; j < 4; j++) acc[i][j] = 0ull;

    int am = tid >> 2, akq = tid & 3;     // A staging: row am, k-quad akq
    int wkr = tid >> 4, wn4 = tid & 15;   // W staging: row wkr, n-quad wn4
    const float* Arow = A + (size_t)(m0 + am) * lda;

    for (int kt = 0; kt < Kpad; kt += 16) {
        // stage A (always in-bounds: Kpad multiple of 16, rows padded/zeroed)
        float4 av = *reinterpret_cast<const float4*>(Arow + kt + 4 * akq);
        *reinterpret_cast<float2*>(&sA[2 * akq + 0][am]) = make_float2(av.x, av.y);
        *reinterpret_cast<float2*>(&sA[2 * akq + 1][am]) = make_float2(av.z, av.w);
        // stage W (guard k >= Kreal)
        int kg = kt + wkr;
        float4 wv = make_float4(0.f, 0.f, 0.f, 0.f);
        if (kg < Kreal)
            wv = *reinterpret_cast<const float4*>(W + (size_t)kg * N + n0 + 4 * wn4);
        {
            float* fB = reinterpret_cast<float*>(&sB[wkr >> 1][0]);
            int p = wkr & 1;
            fB[(4 * wn4 + 0) * 2 + p] = wv.x;
            fB[(4 * wn4 + 1) * 2 + p] = wv.y;
            fB[(4 * wn4 + 2) * 2 + p] = wv.z;
            fB[(4 * wn4 + 3) * 2 + p] = wv.w;
        }
        __syncthreads();
#pragma unroll
        for (int k2 = 0; k2 < 8; k2++) {
            u64 a0 = sA[k2][ty * 4 + 0];
            u64 a1 = sA[k2][ty * 4 + 1];
            u64 a2 = sA[k2][ty * 4 + 2];
            u64 a3 = sA[k2][ty * 4 + 3];
            u64 b0 = sB[k2][tx * 4 + 0];
            u64 b1 = sB[k2][tx * 4 + 1];
            u64 b2 = sB[k2][tx * 4 + 2];
            u64 b3 = sB[k2][tx * 4 + 3];
            acc[0][0] = ffma2(a0, b0, acc[0][0]); acc[0][1] = ffma2(a0, b1, acc[0][1]);
            acc[0][2] = ffma2(a0, b2, acc[0][2]); acc[0][3] = ffma2(a0, b3, acc[0][3]);
            acc[1][0] = ffma2(a1, b0, acc[1][0]); acc[1][1] = ffma2(a1, b1, acc[1][1]);
            acc[1][2] = ffma2(a1, b2, acc[1][2]); acc[1][3] = ffma2(a1, b3, acc[1][3]);
            acc[2][0] = ffma2(a2, b0, acc[2][0]); acc[2][1] = ffma2(a2, b1, acc[2][1]);
            acc[2][2] = ffma2(a2, b2, acc[2][2]); acc[2][3] = ffma2(a2, b3, acc[2][3]);
            acc[3][0] = ffma2(a3, b0, acc[3][0]); acc[3][1] = ffma2(a3, b1, acc[3][1]);
            acc[3][2] = ffma2(a3, b2, acc[3][2]); acc[3][3] = ffma2(a3, b3, acc[3][3]);
        }
        __syncthreads();
    }

#pragma unroll
    for (int i = 0; i < 4; i++) {
        int m = m0 + ty * 4 + i;
        int n = n0 + tx * 4;
        float4 outv;
        outv.x = lo32(acc[i][0]) + hi32(acc[i][0]) + bias[n + 0];
        outv.y = lo32(acc[i][1]) + hi32(acc[i][1]) + bias[n + 1];
        outv.z = lo32(acc[i][2]) + hi32(acc[i][2]) + bias[n + 2];
        outv.w = lo32(acc[i][3]) + hi32(acc[i][3]) + bias[n + 3];
        *reinterpret_cast<float4*>(C + (size_t)m * N + n) = outv;
    }
}

// ---------------- fused per-step LSTM cell ----------------------------------
// 128 blocks x 256 threads. Thread = (batch b, unit u): computes all 4 gates.
// h_prev is staged to SMEM once per block (coalesced), then read as k-pairs.
__global__ void __launch_bounds__(256) lstm_step(
    const float* __restrict__ WhP,   // [2048][512], row = u*4+g
    const float* __restrict__ Zx,    // [B][2048] precomputed x@Wx + b for this t
    const float* __restrict__ h_prev,// [B][H]
    float* __restrict__ h_out,       // [B][H]
    float* __restrict__ c_st)        // [B][H] in/out
{
    __shared__ u64 sh[BB][HH / 2];   // h_prev as k-pairs, 128 KB/… no: 64*256*8 = 128KB? -> 64*256*8B = 131072B too big
    // NOTE: full staging would be 128 KB — exceeds SMEM. Stage per-batch-slice instead.
    // We instead keep direct loads for h (L1-resident after first touch) — see below.
    (void)sh;

    int tid = threadIdx.x;
    int b = tid & 63;
    int ug = tid >> 6;                  // 0..3
    int u = (blockIdx.x << 2) + ug;     // hidden unit

    const ulonglong2* hp = reinterpret_cast<const ulonglong2*>(h_prev + (size_t)b * HH);
    const ulonglong2* wi = reinterpret_cast<const ulonglong2*>(WhP + (size_t)(u * 4 + 0) * HH);
    const ulonglong2* wf = reinterpret_cast<const ulonglong2*>(WhP + (size_t)(u * 4 + 1) * HH);
    const ulonglong2* wg = reinterpret_cast<const ulonglong2*>(WhP + (size_t)(u * 4 + 2) * HH);
    const ulonglong2* wo = reinterpret_cast<const ulonglong2*>(WhP + (size_t)(u * 4 + 3) * HH);

    u64 ai = 0ull, af = 0ull, ag = 0ull, ao = 0ull;  // k-paired partial sums

#pragma unroll 4
    for (int k4 = 0; k4 < HH / 4; k4++) {
        ulonglong2 hv = __ldg(hp + k4);
        ulonglong2 vi = __ldg(wi + k4);
        ulonglong2 vf = __ldg(wf + k4);
        ulonglong2 vg = __ldg(wg + k4);
        ulonglong2 vo = __ldg(wo + k4);
        ai = ffma2(hv.x, vi.x, ai); ai = ffma2(hv.y, vi.y, ai);
        af = ffma2(hv.x, vf.x, af); af = ffma2(hv.y, vf.y, af);
        ag = ffma2(hv.x, vg.x, ag); ag = ffma2(hv.y, vg.y, ag);
        ao = ffma2(hv.x, vo.x, ao); ao = ffma2(hv.y, vo.y, ao);
    }

    const float* zrow = Zx + (size_t)b * G4;
    float zi = lo32(ai) + hi32(ai) + zrow[u];
    float zf = lo32(af) + hi32(af) + zrow[HH + u];
    float zg = lo32(ag) + hi32(ag) + zrow[2 * HH + u];
    float zo = lo32(ao) + hi32(ao) + zrow[3 * HH + u];

    size_t bu = (size_t)b * HH + u;
    float c = c_st[bu];
    float iv = sigmoidf_(zi);
    float fv = sigmoidf_(zf);
    float gv = zg / (1.f + fabsf(zg));          // softsign
    float cn = fv * c + iv * gv;
    float hn = sigmoidf_(zo) * (cn / (1.f + fabsf(cn)));
    c_st[bu] = cn;
    h_out[bu] = hn;
}

// ---------------- head: dense + BN + PReLU + dense + softmax ----------------
__global__ void head_kernel(
    const float* __restrict__ h3, const float* __restrict__ Wd0,
    const float* __restrict__ bd0, const float* __restrict__ gamma,
    const float* __restrict__ beta, const float* __restrict__ mmean,
    const float* __restrict__ mvar, const float* __restrict__ alpha,
    const float* __restrict__ Wd1, const float* __restrict__ bd1,
    float* __restrict__ out)
{
    __shared__ float shh[HH];
    __shared__ float pr[256];
    __shared__ float lg[LL];
    int b = blockIdx.x, tid = threadIdx.x;

    for (int i = tid; i < HH; i += 256) shh[i] = h3[(size_t)b * HH + i];
    __syncthreads();

    float acc = bd0[tid];
#pragma unroll 8
    for (int k = 0; k < HH; k++) acc += shh[k] * Wd0[k * 256 + tid];
    float bn = (acc - mmean[tid]) * rsqrtf(mvar[tid] + 1e-3f) * gamma[tid] + beta[tid];
    pr[tid] = bn >= 0.f ? bn : alpha[tid] * bn;
    __syncthreads();

    if (tid < LL) {
        float l = bd1[tid];
#pragma unroll 8
        for (int j = 0; j < 256; j++) l += pr[j] * Wd1[j * LL + tid];
        lg[tid] = l;
    }
    __syncthreads();

    if (tid == 0) {
        float mx = lg[0];
        for (int l = 1; l < LL; l++) mx = fmaxf(mx, lg[l]);
        float e[LL];
        float s = 0.f;
        for (int l = 0; l < LL; l++) { e[l] = __expf(lg[l] - mx); s += e[l]; }
        float inv = 1.f / s;
        for (int l = 0; l < LL; l++) out[(size_t)b * LL + l] = e[l] * inv;
    }
}

// ---------------- launch ----------------------------------------------------
extern "C" void kernel_launch(void* const* d_in, const int* in_sizes, int n_in,
                              void* d_out, int out_size)
{
    const int*   ids  = (const int*)  d_in[0];
    const float* emb  = (const float*)d_in[1];
    const float* Wx1  = (const float*)d_in[2];
    const float* Wh1  = (const float*)d_in[3];
    const float* b1   = (const float*)d_in[4];
    const float* Wx2  = (const float*)d_in[5];
    const float* Wh2  = (const float*)d_in[6];
    const float* b2   = (const float*)d_in[7];
    const float* Wx3  = (const float*)d_in[8];
    const float* Wh3  = (const float*)d_in[9];
    const float* b3   = (const float*)d_in[10];
    const float* Wd0  = (const float*)d_in[11];
    const float* bd0  = (const float*)d_in[12];
    const float* gmm  = (const float*)d_in[13];
    const float* beta = (const float*)d_in[14];
    const float* mmean= (const float*)d_in[15];
    const float* mvar = (const float*)d_in[16];
    const float* alp  = (const float*)d_in[17];
    const float* Wd1  = (const float*)d_in[18];
    const float* bd1  = (const float*)d_in[19];
    float* out = (float*)d_out;

    float *X, *Z, *Hb, *Cb, *WhP;
    cudaGetSymbolAddress((void**)&X,   g_X);
    cudaGetSymbolAddress((void**)&Z,   g_Z);
    cudaGetSymbolAddress((void**)&Hb,  g_H);
    cudaGetSymbolAddress((void**)&Cb,  g_C);
    cudaGetSymbolAddress((void**)&WhP, g_WhP);

    // weight permutation + embedding gather
    prep_whp<<<G4, 256>>>(Wh1, 0);
    prep_whp<<<G4, 256>>>(Wh2, 1);
    prep_whp<<<G4, 256>>>(Wh3, 2);
    {
        size_t tot = (size_t)TT * BB * DP;
        gather_kernel<<<(unsigned)((tot + 255) / 256), 256>>>(ids, emb);
    }

    cudaMemsetAsync(Hb, 0, (size_t)BB * HH * sizeof(float));   // h slot 0 = zeros
    cudaMemsetAsync(Cb, 0, (size_t)BB * HH * sizeof(float));

    dim3 gg(G4 / 64, (TT * BB) / 64);

    // ---- layer 1 ----
    gemm_bias<<<gg, 256>>>(X, DP, Wx1, b1, Z, G4, DP, DD);
    for (int t = 0; t < TT; t++)
        lstm_step<<<HH / 4, 256>>>(WhP + 0 * (size_t)G4 * HH,
                                   Z + (size_t)t * BB * G4,
                                   Hb + (size_t)t * BB * HH,
                                   Hb + (size_t)(t + 1) * BB * HH, Cb);

    // ---- layer 2 ----
    gemm_bias<<<gg, 256>>>(Hb + (size_t)BB * HH, HH, Wx2, b2, Z, G4, HH, HH);
    cudaMemsetAsync(Cb, 0, (size_t)BB * HH * sizeof(float));
    for (int t = 0; t < TT; t++)
        lstm_step<<<HH / 4, 256>>>(WhP + 1 * (size_t)G4 * HH,
                                   Z + (size_t)t * BB * G4,
                                   Hb + (size_t)t * BB * HH,
                                   Hb + (size_t)(t + 1) * BB * HH, Cb);

    // ---- layer 3 ----
    gemm_bias<<<gg, 256>>>(Hb + (size_t)BB * HH, HH, Wx3, b3, Z, G4, HH, HH);
    cudaMemsetAsync(Cb, 0, (size_t)BB * HH * sizeof(float));
    for (int t = 0; t < TT; t++)
        lstm_step<<<HH / 4, 256>>>(WhP + 2 * (size_t)G4 * HH,
                                   Z + (size_t)t * BB * G4,
                                   Hb + (size_t)t * BB * HH,
                                   Hb + (size_t)(t + 1) * BB * HH, Cb);

    // ---- head ----
    head_kernel<<<BB, 256>>>(Hb + (size_t)TT * BB * HH, Wd0, bd0, gmm, beta,
                             mmean, mvar, alp, Wd1, bd1, out);
}

// round 4
// speedup vs baseline: 1.3330x; 1.3330x over previous
#include <cuda_runtime.h>
#include <cstdint>

typedef unsigned long long u64;

#define TT 200
#define BB 64
#define DD 300
#define DP 304
#define HH 512
#define G4 2048
#define LL 7

// ---------------- scratch (static device allocations; no cudaMalloc) --------
__device__ float g_X[(size_t)TT * BB * DP];          // gathered embeddings, padded K
__device__ float g_Z[(size_t)TT * BB * G4];          // input-projection buffer (reused per layer)
__device__ float g_H[(size_t)(TT + 1) * BB * HH];    // hidden states, slot 0 = zeros
__device__ float g_CT[HH * BB];                      // cell state, TRANSPOSED [u][b]
__device__ float g_WhP[3][(size_t)G4 * HH];          // permuted recurrent weights [u*4+g][k]

// ---------------- helpers ---------------------------------------------------
__device__ __forceinline__ u64 ffma2(u64 a, u64 b, u64 c) {
    u64 d;
    asm("fma.rn.f32x2 %0, %1, %2, %3;" : "=l"(d) : "l"(a), "l"(b), "l"(c));
    return d;
}
__device__ __forceinline__ float lo32(u64 v) { return __uint_as_float((unsigned)v); }
__device__ __forceinline__ float hi32(u64 v) { return __uint_as_float((unsigned)(v >> 32)); }
__device__ __forceinline__ float sigmoidf_(float x) { return 1.f / (1.f + __expf(-x)); }

// ---------------- embedding gather (time-major, zero-padded K) --------------
__global__ void gather_kernel(const int* __restrict__ ids, const float* __restrict__ emb) {
    size_t idx = (size_t)blockIdx.x * 256 + threadIdx.x;
    if (idx >= (size_t)TT * BB * DP) return;
    int d = (int)(idx % DP);
    int tb = (int)(idx / DP);
    int t = tb / BB, b = tb % BB;
    float v = 0.f;
    if (d < DD) {
        int id = ids[b * TT + t];
        v = emb[(size_t)id * DD + d];
    }
    g_X[idx] = v;
}

// ---------------- permute Wh[k][g*512+u] -> WhP[u*4+g][k] -------------------
__global__ void prep_whp(const float* __restrict__ Wh, int layer) {
    int r = blockIdx.x;            // 0..2047
    int u = r >> 2, g = r & 3;
    int col = g * HH + u;
    for (int k = threadIdx.x; k < HH; k += 256)
        g_WhP[layer][(size_t)r * HH + k] = Wh[(size_t)k * G4 + col];
}

// ---------------- tiled fp32 GEMM with bias:  C[M,N] = A[M,K]@W[K,N] + b ----
__global__ void __launch_bounds__(256) gemm_bias(
    const float* __restrict__ A, int lda,
    const float* __restrict__ W, const float* __restrict__ bias,
    float* __restrict__ C, int N, int Kpad, int Kreal)
{
    __shared__ u64 sA[8][64];   // [k2][m]   pairs over k
    __shared__ u64 sB[8][64];   // [k2][n]   pairs over k

    int tid = threadIdx.x;
    int n0 = blockIdx.x * 64, m0 = blockIdx.y * 64;
    int tx = tid & 15, ty = tid >> 4;

    u64 acc[4][4];
#pragma unroll
    for (int i = 0; i < 4; i++)
#pragma unroll
        for (int j = 0; j < 4; j++) acc[i][j] = 0ull;

    int am = tid >> 2, akq = tid & 3;     // A staging: row am, k-quad akq
    int wkr = tid >> 4, wn4 = tid & 15;   // W staging: row wkr, n-quad wn4
    const float* Arow = A + (size_t)(m0 + am) * lda;

    for (int kt = 0; kt < Kpad; kt += 16) {
        float4 av = *reinterpret_cast<const float4*>(Arow + kt + 4 * akq);
        *reinterpret_cast<float2*>(&sA[2 * akq + 0][am]) = make_float2(av.x, av.y);
        *reinterpret_cast<float2*>(&sA[2 * akq + 1][am]) = make_float2(av.z, av.w);
        int kg = kt + wkr;
        float4 wv = make_float4(0.f, 0.f, 0.f, 0.f);
        if (kg < Kreal)
            wv = *reinterpret_cast<const float4*>(W + (size_t)kg * N + n0 + 4 * wn4);
        {
            float* fB = reinterpret_cast<float*>(&sB[wkr >> 1][0]);
            int p = wkr & 1;
            fB[(4 * wn4 + 0) * 2 + p] = wv.x;
            fB[(4 * wn4 + 1) * 2 + p] = wv.y;
            fB[(4 * wn4 + 2) * 2 + p] = wv.z;
            fB[(4 * wn4 + 3) * 2 + p] = wv.w;
        }
        __syncthreads();
#pragma unroll
        for (int k2 = 0; k2 < 8; k2++) {
            u64 a0 = sA[k2][ty * 4 + 0];
            u64 a1 = sA[k2][ty * 4 + 1];
            u64 a2 = sA[k2][ty * 4 + 2];
            u64 a3 = sA[k2][ty * 4 + 3];
            u64 b0 = sB[k2][tx * 4 + 0];
            u64 b1 = sB[k2][tx * 4 + 1];
            u64 b2 = sB[k2][tx * 4 + 2];
            u64 b3 = sB[k2][tx * 4 + 3];
            acc[0][0] = ffma2(a0, b0, acc[0][0]); acc[0][1] = ffma2(a0, b1, acc[0][1]);
            acc[0][2] = ffma2(a0, b2, acc[0][2]); acc[0][3] = ffma2(a0, b3, acc[0][3]);
            acc[1][0] = ffma2(a1, b0, acc[1][0]); acc[1][1] = ffma2(a1, b1, acc[1][1]);
            acc[1][2] = ffma2(a1, b2, acc[1][2]); acc[1][3] = ffma2(a1, b3, acc[1][3]);
            acc[2][0] = ffma2(a2, b0, acc[2][0]); acc[2][1] = ffma2(a2, b1, acc[2][1]);
            acc[2][2] = ffma2(a2, b2, acc[2][2]); acc[2][3] = ffma2(a2, b3, acc[2][3]);
            acc[3][0] = ffma2(a3, b0, acc[3][0]); acc[3][1] = ffma2(a3, b1, acc[3][1]);
            acc[3][2] = ffma2(a3, b2, acc[3][2]); acc[3][3] = ffma2(a3, b3, acc[3][3]);
        }
        __syncthreads();
    }

#pragma unroll
    for (int i = 0; i < 4; i++) {
        int m = m0 + ty * 4 + i;
        int n = n0 + tx * 4;
        float4 outv;
        outv.x = lo32(acc[i][0]) + hi32(acc[i][0]) + bias[n + 0];
        outv.y = lo32(acc[i][1]) + hi32(acc[i][1]) + bias[n + 1];
        outv.z = lo32(acc[i][2]) + hi32(acc[i][2]) + bias[n + 2];
        outv.w = lo32(acc[i][3]) + hi32(acc[i][3]) + bias[n + 3];
        *reinterpret_cast<float4*>(C + (size_t)m * N + n) = outv;
    }
}

// ---------------- fused per-step LSTM cell (v2: SMEM-staged h + Z) ----------
// 128 blocks x 256 threads. Thread = (b = tid&63, ug = tid>>6), u = blk*4+ug.
// h staged per k-tile (128 k) into transposed padded SMEM; Z slice staged once.
__global__ void __launch_bounds__(256) lstm_step(
    const float* __restrict__ WhP,   // [2048][512], row = u*4+g
    const float* __restrict__ Zx,    // [B][2048] precomputed x@Wx + b for this t
    const float* __restrict__ h_prev,// [B][H]
    float* __restrict__ h_out,       // [B][H]
    float* __restrict__ cT)          // [H][B] in/out (transposed)
{
    __shared__ u64   shp[64][65];    // h pairs: shp[kp][b], kp = k-pair in tile
    __shared__ float sZ[16][64];     // sZ[g*4+ug][b]

    int tid = threadIdx.x;
    int b  = tid & 63;
    int ug = tid >> 6;                  // 0..3
    int u0 = blockIdx.x << 2;
    int u  = u0 + ug;

    // stage Z slice: thread (g = tid>>6, bb = tid&63) loads float4 at [bb][g*512+u0]
    {
        int g = tid >> 6, bb = tid & 63;
        float4 zv = *reinterpret_cast<const float4*>(Zx + (size_t)bb * G4 + g * HH + u0);
        sZ[g * 4 + 0][bb] = zv.x;
        sZ[g * 4 + 1][bb] = zv.y;
        sZ[g * 4 + 2][bb] = zv.z;
        sZ[g * 4 + 3][bb] = zv.w;
    }

    const u64* hp64 = reinterpret_cast<const u64*>(h_prev);   // [b][256 pairs]

    u64 ai = 0ull, af = 0ull, ag_ = 0ull, ao = 0ull;

#pragma unroll
    for (int kt = 0; kt < 4; kt++) {
        // stage h tile: coalesced gmem read, transposed SMEM write
        __syncthreads();
#pragma unroll
        for (int j = 0; j < 16; j++) {
            int idx = tid + 256 * j;           // 0..4095
            int b2 = idx >> 6, kp = idx & 63;
            shp[kp][b2] = hp64[(size_t)b2 * 256 + kt * 64 + kp];
        }
        __syncthreads();

        const ulonglong2* wi2 = reinterpret_cast<const ulonglong2*>(WhP + (size_t)(u * 4 + 0) * HH + kt * 128);
        const ulonglong2* wf2 = reinterpret_cast<const ulonglong2*>(WhP + (size_t)(u * 4 + 1) * HH + kt * 128);
        const ulonglong2* wg2 = reinterpret_cast<const ulonglong2*>(WhP + (size_t)(u * 4 + 2) * HH + kt * 128);
        const ulonglong2* wo2 = reinterpret_cast<const ulonglong2*>(WhP + (size_t)(u * 4 + 3) * HH + kt * 128);

#pragma unroll 8
        for (int q = 0; q < 32; q++) {
            u64 h0 = shp[2 * q + 0][b];
            u64 h1 = shp[2 * q + 1][b];
            ulonglong2 vi = __ldg(wi2 + q);
            ulonglong2 vf = __ldg(wf2 + q);
            ulonglong2 vg = __ldg(wg2 + q);
            ulonglong2 vo = __ldg(wo2 + q);
            ai  = ffma2(h0, vi.x, ai);  ai  = ffma2(h1, vi.y, ai);
            af  = ffma2(h0, vf.x, af);  af  = ffma2(h1, vf.y, af);
            ag_ = ffma2(h0, vg.x, ag_); ag_ = ffma2(h1, vg.y, ag_);
            ao  = ffma2(h0, vo.x, ao);  ao  = ffma2(h1, vo.y, ao);
        }
    }

    float zi = lo32(ai)  + hi32(ai)  + sZ[0 * 4 + ug][b];
    float zf = lo32(af)  + hi32(af)  + sZ[1 * 4 + ug][b];
    float zg = lo32(ag_) + hi32(ag_) + sZ[2 * 4 + ug][b];
    float zo = lo32(ao)  + hi32(ao)  + sZ[3 * 4 + ug][b];

    int ub = u * BB + b;                 // transposed cell index, coalesced
    float c = cT[ub];
    float iv = sigmoidf_(zi);
    float fv = sigmoidf_(zf);
    float gv = zg / (1.f + fabsf(zg));          // softsign
    float cn = fv * c + iv * gv;
    float hn = sigmoidf_(zo) * (cn / (1.f + fabsf(cn)));
    cT[ub] = cn;
    h_out[(size_t)b * HH + u] = hn;      // scatter (32 lines/warp) — once per step
}

// ---------------- head: dense + BN + PReLU + dense + softmax ----------------
__global__ void head_kernel(
    const float* __restrict__ h3, const float* __restrict__ Wd0,
    const float* __restrict__ bd0, const float* __restrict__ gamma,
    const float* __restrict__ beta, const float* __restrict__ mmean,
    const float* __restrict__ mvar, const float* __restrict__ alpha,
    const float* __restrict__ Wd1, const float* __restrict__ bd1,
    float* __restrict__ out)
{
    __shared__ float shh[HH];
    __shared__ float pr[256];
    __shared__ float lg[LL];
    int b = blockIdx.x, tid = threadIdx.x;

    for (int i = tid; i < HH; i += 256) shh[i] = h3[(size_t)b * HH + i];
    __syncthreads();

    float acc = bd0[tid];
#pragma unroll 8
    for (int k = 0; k < HH; k++) acc += shh[k] * Wd0[k * 256 + tid];
    float bn = (acc - mmean[tid]) * rsqrtf(mvar[tid] + 1e-3f) * gamma[tid] + beta[tid];
    pr[tid] = bn >= 0.f ? bn : alpha[tid] * bn;
    __syncthreads();

    if (tid < LL) {
        float l = bd1[tid];
#pragma unroll 8
        for (int j = 0; j < 256; j++) l += pr[j] * Wd1[j * LL + tid];
        lg[tid] = l;
    }
    __syncthreads();

    if (tid == 0) {
        float mx = lg[0];
        for (int l = 1; l < LL; l++) mx = fmaxf(mx, lg[l]);
        float e[LL];
        float s = 0.f;
        for (int l = 0; l < LL; l++) { e[l] = __expf(lg[l] - mx); s += e[l]; }
        float inv = 1.f / s;
        for (int l = 0; l < LL; l++) out[(size_t)b * LL + l] = e[l] * inv;
    }
}

// ---------------- launch ----------------------------------------------------
extern "C" void kernel_launch(void* const* d_in, const int* in_sizes, int n_in,
                              void* d_out, int out_size)
{
    const int*   ids  = (const int*)  d_in[0];
    const float* emb  = (const float*)d_in[1];
    const float* Wx1  = (const float*)d_in[2];
    const float* Wh1  = (const float*)d_in[3];
    const float* b1   = (const float*)d_in[4];
    const float* Wx2  = (const float*)d_in[5];
    const float* Wh2  = (const float*)d_in[6];
    const float* b2   = (const float*)d_in[7];
    const float* Wx3  = (const float*)d_in[8];
    const float* Wh3  = (const float*)d_in[9];
    const float* b3   = (const float*)d_in[10];
    const float* Wd0  = (const float*)d_in[11];
    const float* bd0  = (const float*)d_in[12];
    const float* gmm  = (const float*)d_in[13];
    const float* beta = (const float*)d_in[14];
    const float* mmean= (const float*)d_in[15];
    const float* mvar = (const float*)d_in[16];
    const float* alp  = (const float*)d_in[17];
    const float* Wd1  = (const float*)d_in[18];
    const float* bd1  = (const float*)d_in[19];
    float* out = (float*)d_out;

    float *X, *Z, *Hb, *CbT, *WhP;
    cudaGetSymbolAddress((void**)&X,   g_X);
    cudaGetSymbolAddress((void**)&Z,   g_Z);
    cudaGetSymbolAddress((void**)&Hb,  g_H);
    cudaGetSymbolAddress((void**)&CbT, g_CT);
    cudaGetSymbolAddress((void**)&WhP, g_WhP);

    prep_whp<<<G4, 256>>>(Wh1, 0);
    prep_whp<<<G4, 256>>>(Wh2, 1);
    prep_whp<<<G4, 256>>>(Wh3, 2);
    {
        size_t tot = (size_t)TT * BB * DP;
        gather_kernel<<<(unsigned)((tot + 255) / 256), 256>>>(ids, emb);
    }

    cudaMemsetAsync(Hb, 0, (size_t)BB * HH * sizeof(float));   // h slot 0 = zeros
    cudaMemsetAsync(CbT, 0, (size_t)HH * BB * sizeof(float));

    dim3 gg(G4 / 64, (TT * BB) / 64);

    // ---- layer 1 ----
    gemm_bias<<<gg, 256>>>(X, DP, Wx1, b1, Z, G4, DP, DD);
    for (int t = 0; t < TT; t++)
        lstm_step<<<HH / 4, 256>>>(WhP + 0 * (size_t)G4 * HH,
                                   Z + (size_t)t * BB * G4,
                                   Hb + (size_t)t * BB * HH,
                                   Hb + (size_t)(t + 1) * BB * HH, CbT);

    // ---- layer 2 ----
    gemm_bias<<<gg, 256>>>(Hb + (size_t)BB * HH, HH, Wx2, b2, Z, G4, HH, HH);
    cudaMemsetAsync(CbT, 0, (size_t)HH * BB * sizeof(float));
    for (int t = 0; t < TT; t++)
        lstm_step<<<HH / 4, 256>>>(WhP + 1 * (size_t)G4 * HH,
                                   Z + (size_t)t * BB * G4,
                                   Hb + (size_t)t * BB * HH,
                                   Hb + (size_t)(t + 1) * BB * HH, CbT);

    // ---- layer 3 ----
    gemm_bias<<<gg, 256>>>(Hb + (size_t)BB * HH, HH, Wx3, b3, Z, G4, HH, HH);
    cudaMemsetAsync(CbT, 0, (size_t)HH * BB * sizeof(float));
    for (int t = 0; t < TT; t++)
        lstm_step<<<HH / 4, 256>>>(WhP + 2 * (size_t)G4 * HH,
                                   Z + (size_t)t * BB * G4,
                                   Hb + (size_t)t * BB * HH,
                                   Hb + (size_t)(t + 1) * BB * HH, CbT);

    // ---- head ----
    head_kernel<<<BB, 256>>>(Hb + (size_t)TT * BB * HH, Wd0, bd0, gmm, beta,
                             mmean, mvar, alp, Wd1, bd1, out);
}